// round 9
// baseline (speedup 1.0000x reference)
#include <cuda_runtime.h>

#define NB 64
#define LC 4096
#define HD 768
#define PD 128
#define BUDGETF 200.0f
#define CHUNK 64                  // rows per ticket
#define NTICK (NB * (LC / CHUNK)) // 4096 tickets

// Scratch (allocation-free rule: __device__ globals)
__device__ float d_q[NB * PD];      // q_b = qr_b @ Wq + bq
__device__ float d_U[NB * HD];      // u_b = Wc @ q_b
__device__ float d_qbias[NB];       // q_b . bc
__device__ int   d_len[NB];         // valid context length per batch
__device__ float d_s[NB * LC];      // match scores (only [0,len) valid)
__device__ int   d_ticket;          // score work-stealing counter

// ---------------------------------------------------------------------------
// Kernel 1a: q[b,p] = qr[b,:] . Wq[:,p] + bq[p] ; qbias[b] = q_b . bc ;
//            len[b] = sum(mask[b,:]) ; resets d_ticket (stream-ordered).
// ---------------------------------------------------------------------------
__global__ void __launch_bounds__(512) qproj_kernel(const float* __restrict__ qr,
                                                    const float* __restrict__ Wq,
                                                    const float* __restrict__ bq,
                                                    const float* __restrict__ bc,
                                                    const int* __restrict__ mask) {
    int b = blockIdx.x;
    __shared__ float sh_qr[HD];
    __shared__ float sh_part[512];
    __shared__ int sh_cnt[16];
    int tid = threadIdx.x;

    if (b == 0 && tid == 0) d_ticket = 0;   // reset for score_kernel

    for (int i = tid; i < HD; i += 512) sh_qr[i] = qr[b * HD + i];

    int cnt = 0;
    for (int i = tid; i < LC; i += 512) cnt += mask[b * LC + i];
    #pragma unroll
    for (int off = 16; off; off >>= 1) cnt += __shfl_xor_sync(0xffffffffu, cnt, off);
    if ((tid & 31) == 0) sh_cnt[tid >> 5] = cnt;
    __syncthreads();
    if (tid == 0) {
        int t = 0;
        #pragma unroll
        for (int w = 0; w < 16; w++) t += sh_cnt[w];
        d_len[b] = t;
    }

    int p = tid & 127;
    int slice = tid >> 7;            // 0..3
    int h0 = slice * (HD / 4);       // 192 rows per slice
    float a0 = 0.f, a1 = 0.f, a2 = 0.f, a3 = 0.f;
    #pragma unroll 4
    for (int h = h0; h < h0 + HD / 4; h += 4) {
        a0 = fmaf(sh_qr[h + 0], Wq[(h + 0) * PD + p], a0);
        a1 = fmaf(sh_qr[h + 1], Wq[(h + 1) * PD + p], a1);
        a2 = fmaf(sh_qr[h + 2], Wq[(h + 2) * PD + p], a2);
        a3 = fmaf(sh_qr[h + 3], Wq[(h + 3) * PD + p], a3);
    }
    sh_part[tid] = (a0 + a1) + (a2 + a3);
    __syncthreads();

    if (tid < PD) {
        float q = sh_part[tid] + sh_part[PD + tid] + sh_part[2 * PD + tid]
                + sh_part[3 * PD + tid] + bq[tid];
        d_q[b * PD + tid] = q;
        sh_part[tid] = q;
    }
    __syncthreads();

    if (tid < 32) {
        float v = 0.f;
        #pragma unroll
        for (int k = 0; k < 4; k++)
            v = fmaf(sh_part[tid + 32 * k], bc[tid + 32 * k], v);
        #pragma unroll
        for (int off = 16; off; off >>= 1)
            v += __shfl_xor_sync(0xffffffffu, v, off);
        if (tid == 0) d_qbias[b] = v;
    }
}

// ---------------------------------------------------------------------------
// Kernel 1b: u[b,h] = Wc[h,:] . q_b  (warp per h, lanes over p; grid 64x4)
// ---------------------------------------------------------------------------
__global__ void __launch_bounds__(256) uproj_kernel(const float* __restrict__ Wc) {
    int b = blockIdx.x;
    int chunk = blockIdx.y;
    __shared__ float sh_q[PD];
    int tid = threadIdx.x;
    if (tid < PD) sh_q[tid] = d_q[b * PD + tid];
    __syncthreads();

    int warp = tid >> 5, lane = tid & 31;
    for (int hh = warp; hh < HD / 4; hh += 8) {
        int h = chunk * (HD / 4) + hh;
        const float* wr = Wc + (size_t)h * PD;
        float acc = wr[lane] * sh_q[lane];
        acc = fmaf(wr[lane + 32], sh_q[lane + 32], acc);
        acc = fmaf(wr[lane + 64], sh_q[lane + 64], acc);
        acc = fmaf(wr[lane + 96], sh_q[lane + 96], acc);
        #pragma unroll
        for (int off = 16; off; off >>= 1)
            acc += __shfl_xor_sync(0xffffffffu, acc, off);
        if (lane == 0) d_U[b * HD + h] = acc;
    }
}

// ---------------------------------------------------------------------------
// Kernel 2: s[b,j] = ctx[b,j,:].u_b + qbias for j < len[b].
// Dynamic work-stealing over 64-row tickets (kills stride-tail imbalance).
// Inner loop identical to the measured-fast round-4 form.
// ---------------------------------------------------------------------------
#define SCORE_BLOCKS 1184

__global__ void __launch_bounds__(256) score_kernel(const float* __restrict__ ctx) {
    __shared__ float sh_u[HD];
    __shared__ int sh_ticket;
    int tid = threadIdx.x;
    int warp = tid >> 5, lane = tid & 31;

    for (;;) {
        if (tid == 0) sh_ticket = atomicAdd(&d_ticket, 1);
        __syncthreads();                 // sh_ticket visible; prior sh_u reads done
        int t = sh_ticket;
        __syncthreads();                 // protect sh_ticket before next write
        if (t >= NTICK) break;           // uniform across block

        int b = t >> 6;                  // LC/CHUNK = 64 tickets per batch
        int j0 = (t & 63) * CHUNK;
        int len = d_len[b];
        if (j0 >= len) continue;         // cheap skip, grab next ticket

        for (int i = tid; i < HD; i += 256) sh_u[i] = d_U[b * HD + i];
        __syncthreads();

        int nv = min(CHUNK, len - j0);
        float bias = d_qbias[b];
        const float4* u4 = (const float4*)sh_u;

        for (int r = warp; r < nv; r += 8) {
            int j = j0 + r;
            const float4* row = (const float4*)(ctx + ((size_t)b * LC + j) * HD);
            float acc = 0.f;
            #pragma unroll
            for (int i = 0; i < 6; i++) {       // 192 float4 / 32 lanes
                float4 v = __ldcs(row + lane + 32 * i);
                float4 w = u4[lane + 32 * i];
                acc = fmaf(v.x, w.x, acc);
                acc = fmaf(v.y, w.y, acc);
                acc = fmaf(v.z, w.z, acc);
                acc = fmaf(v.w, w.w, acc);
            }
            #pragma unroll
            for (int off = 16; off; off >>= 1)
                acc += __shfl_xor_sync(0xffffffffu, acc, off);
            if (lane == 0) d_s[b * LC + j] = acc + bias;
        }
        // no trailing barrier: next iteration's first __syncthreads orders
        // sh_u reads before the next sh_u overwrite.
    }
}

// ---------------------------------------------------------------------------
// Kernel 3: tau solve (8-ary, 8 rounds, double-buffered partials) + scatter.
// ---------------------------------------------------------------------------
__device__ __forceinline__ float clip01(float v) {
    return fminf(fmaxf(v, 0.f), 1.f);
}

__global__ void __launch_bounds__(512) tau_kernel(const int* __restrict__ qe_arr,
                                                  float* __restrict__ out) {
    int b = blockIdx.x;
    const int NT = 512;
    __shared__ float redf[2][16 * 7];    // [parity][warp*7 + c]
    int tid = threadIdx.x, warp = tid >> 5, lane = tid & 31;
    int len = d_len[b];
    const float* sp = d_s + b * LC;

    float v[8];
    #pragma unroll
    for (int k = 0; k < 8; k++) {
        int i = tid + k * NT;
        v[k] = (i < len) ? sp[i] : -100000.0f;
    }

    float mx = -100000.0f, sum0 = 0.f;
    #pragma unroll
    for (int k = 0; k < 8; k++) {
        mx = fmaxf(mx, v[k]);
        sum0 += clip01(v[k]);
    }
    #pragma unroll
    for (int off = 16; off; off >>= 1) {
        mx   = fmaxf(mx, __shfl_xor_sync(0xffffffffu, mx, off));
        sum0 += __shfl_xor_sync(0xffffffffu, sum0, off);
    }
    if (lane == 0) { redf[0][warp * 2] = mx; redf[0][warp * 2 + 1] = sum0; }
    __syncthreads();
    {
        float a = redf[0][0], s = redf[0][1];
        #pragma unroll
        for (int w = 1; w < 16; w++) {
            a = fmaxf(a, redf[0][w * 2]);
            s += redf[0][w * 2 + 1];
        }
        mx = a; sum0 = s;
    }
    __syncthreads();

    float tau = 0.f;
    if (sum0 > BUDGETF) {
        float lo = 0.f, hi = mx;
        for (int it = 0; it < 8; it++) {
            float* buf = redf[it & 1];
            float step = (hi - lo) * 0.125f;
            float part[7];
            #pragma unroll
            for (int c = 0; c < 7; c++) part[c] = 0.f;
            #pragma unroll
            for (int k = 0; k < 8; k++) {
                float x = v[k] - lo;
                #pragma unroll
                for (int c = 0; c < 7; c++)
                    part[c] += clip01(x - (c + 1) * step);
            }
            #pragma unroll
            for (int c = 0; c < 7; c++) {
                #pragma unroll
                for (int off = 16; off; off >>= 1)
                    part[c] += __shfl_xor_sync(0xffffffffu, part[c], off);
            }
            if (lane == 0) {
                #pragma unroll
                for (int c = 0; c < 7; c++) buf[warp * 7 + c] = part[c];
            }
            __syncthreads();
            float tot[7];
            #pragma unroll
            for (int c = 0; c < 7; c++) tot[c] = buf[c];
            #pragma unroll
            for (int w = 1; w < 16; w++) {
                #pragma unroll
                for (int c = 0; c < 7; c++) tot[c] += buf[w * 7 + c];
            }
            float nlo = lo, nhi = hi;
            bool crossed = false;
            #pragma unroll
            for (int c = 0; c < 7; c++) {
                float tc = lo + (c + 1) * step;
                if (!crossed) {
                    if (tot[c] > BUDGETF) nlo = tc;
                    else { nhi = tc; crossed = true; }
                }
            }
            lo = nlo; hi = nhi;
        }
        tau = 0.5f * (lo + hi);
    }

    int qe = qe_arr[b];
    int clen = len - 1;
    for (int p = tid; p < LC; p += NT) {
        float r;
        if (p < qe) {
            r = 1.f;
        } else {
            int idx = p - qe + 1;                 // >= 1
            r = (idx <= clen) ? clip01(sp[idx] - tau) : 0.f;
        }
        out[b * LC + p] = r;
    }
}

// ---------------------------------------------------------------------------
extern "C" void kernel_launch(void* const* d_in, const int* in_sizes, int n_in,
                              void* d_out, int out_size) {
    const float* question = (const float*)d_in[0];  // [B,1,H]
    const float* context  = (const float*)d_in[1];  // [B,LC,H]
    const float* Wq       = (const float*)d_in[2];  // [H,P]
    const float* bq       = (const float*)d_in[3];  // [P]
    const float* Wc       = (const float*)d_in[4];  // [H,P]
    const float* bc       = (const float*)d_in[5];  // [P]
    const int*   maskp    = (const int*)d_in[6];    // [B,LC]
    const int*   qep      = (const int*)d_in[7];    // [B]
    float* out = (float*)d_out;                     // [B,MAXLEN]

    qproj_kernel<<<NB, 512>>>(question, Wq, bq, bc, maskp);
    dim3 gu(NB, 4);
    uproj_kernel<<<gu, 256>>>(Wc);
    score_kernel<<<SCORE_BLOCKS, 256>>>(context);
    tau_kernel<<<NB, 512>>>(qep, out);
}

// round 10
// speedup vs baseline: 1.0704x; 1.0704x over previous
#include <cuda_runtime.h>

#define NB 64
#define LC 4096
#define HD 768
#define PD 128
#define BUDGETF 200.0f
#define NCHUNK 32                 // LC / 128 chunks per batch

// Scratch (allocation-free rule: __device__ globals)
__device__ float d_q[NB * PD];      // q_b = qr_b @ Wq + bq
__device__ float d_U[NB * HD];      // u_b = Wc @ q_b
__device__ float d_qbias[NB];       // q_b . bc
__device__ int   d_len[NB];         // valid context length per batch
__device__ float d_s[NB * LC];      // match scores (only [0,len) valid)

// ---------------------------------------------------------------------------
// Kernel 1a: q[b,p] = qr[b,:] . Wq[:,p] + bq[p] ; qbias[b] = q_b . bc ;
//            len[b] = sum(mask[b,:])      (measured-fast round-4 form)
// ---------------------------------------------------------------------------
__global__ void __launch_bounds__(512) qproj_kernel(const float* __restrict__ qr,
                                                    const float* __restrict__ Wq,
                                                    const float* __restrict__ bq,
                                                    const float* __restrict__ bc,
                                                    const int* __restrict__ mask) {
    int b = blockIdx.x;
    __shared__ float sh_qr[HD];
    __shared__ float sh_part[512];
    __shared__ int sh_cnt[16];
    int tid = threadIdx.x;

    for (int i = tid; i < HD; i += 512) sh_qr[i] = qr[b * HD + i];

    int cnt = 0;
    for (int i = tid; i < LC; i += 512) cnt += mask[b * LC + i];
    #pragma unroll
    for (int off = 16; off; off >>= 1) cnt += __shfl_xor_sync(0xffffffffu, cnt, off);
    if ((tid & 31) == 0) sh_cnt[tid >> 5] = cnt;
    __syncthreads();
    if (tid == 0) {
        int t = 0;
        #pragma unroll
        for (int w = 0; w < 16; w++) t += sh_cnt[w];
        d_len[b] = t;
    }

    int p = tid & 127;
    int slice = tid >> 7;            // 0..3
    int h0 = slice * (HD / 4);       // 192 rows per slice
    float a0 = 0.f, a1 = 0.f, a2 = 0.f, a3 = 0.f;
    #pragma unroll 4
    for (int h = h0; h < h0 + HD / 4; h += 4) {
        a0 = fmaf(sh_qr[h + 0], Wq[(h + 0) * PD + p], a0);
        a1 = fmaf(sh_qr[h + 1], Wq[(h + 1) * PD + p], a1);
        a2 = fmaf(sh_qr[h + 2], Wq[(h + 2) * PD + p], a2);
        a3 = fmaf(sh_qr[h + 3], Wq[(h + 3) * PD + p], a3);
    }
    sh_part[tid] = (a0 + a1) + (a2 + a3);
    __syncthreads();

    if (tid < PD) {
        float q = sh_part[tid] + sh_part[PD + tid] + sh_part[2 * PD + tid]
                + sh_part[3 * PD + tid] + bq[tid];
        d_q[b * PD + tid] = q;
        sh_part[tid] = q;
    }
    __syncthreads();

    if (tid < 32) {
        float v = 0.f;
        #pragma unroll
        for (int k = 0; k < 4; k++)
            v = fmaf(sh_part[tid + 32 * k], bc[tid + 32 * k], v);
        #pragma unroll
        for (int off = 16; off; off >>= 1)
            v += __shfl_xor_sync(0xffffffffu, v, off);
        if (tid == 0) d_qbias[b] = v;
    }
}

// ---------------------------------------------------------------------------
// Kernel 1b: u[b,h] = Wc[h,:] . q_b  (warp per h, lanes over p; grid 64x4)
// ---------------------------------------------------------------------------
__global__ void __launch_bounds__(256) uproj_kernel(const float* __restrict__ Wc) {
    int b = blockIdx.x;
    int chunk = blockIdx.y;
    __shared__ float sh_q[PD];
    int tid = threadIdx.x;
    if (tid < PD) sh_q[tid] = d_q[b * PD + tid];
    __syncthreads();

    int warp = tid >> 5, lane = tid & 31;
    for (int hh = warp; hh < HD / 4; hh += 8) {
        int h = chunk * (HD / 4) + hh;
        const float* wr = Wc + (size_t)h * PD;
        float acc = wr[lane] * sh_q[lane];
        acc = fmaf(wr[lane + 32], sh_q[lane + 32], acc);
        acc = fmaf(wr[lane + 64], sh_q[lane + 64], acc);
        acc = fmaf(wr[lane + 96], sh_q[lane + 96], acc);
        #pragma unroll
        for (int off = 16; off; off >>= 1)
            acc += __shfl_xor_sync(0xffffffffu, acc, off);
        if (lane == 0) d_U[b * HD + h] = acc;
    }
}

// ---------------------------------------------------------------------------
// Kernel 2: s[b,j] = ctx[b,j,:].u_b + qbias for j < len[b].
// Grid-stride persistent blocks, static assignment (measured-fast R7 form).
// ---------------------------------------------------------------------------
#define SCORE_BLOCKS 1184

__global__ void __launch_bounds__(256) score_kernel(const float* __restrict__ ctx) {
    __shared__ float sh_u[HD];
    int tid = threadIdx.x;
    int warp = tid >> 5, lane = tid & 31;

    for (int c = blockIdx.x; c < NB * NCHUNK; c += gridDim.x) {
        int b = c >> 5;
        int j0 = (c & 31) * 128;
        int len = d_len[b];
        if (j0 >= len) continue;        // uniform across block

        __syncthreads();                // protect sh_u from previous iteration
        for (int i = tid; i < HD; i += 256) sh_u[i] = d_U[b * HD + i];
        __syncthreads();

        int nv = min(128, len - j0);
        float bias = d_qbias[b];
        const float4* u4 = (const float4*)sh_u;

        for (int r = warp; r < nv; r += 8) {
            int j = j0 + r;
            const float4* row = (const float4*)(ctx + ((size_t)b * LC + j) * HD);
            float acc = 0.f;
            #pragma unroll
            for (int i = 0; i < 6; i++) {       // 192 float4 / 32 lanes
                float4 v = __ldcs(row + lane + 32 * i);
                float4 w = u4[lane + 32 * i];
                acc = fmaf(v.x, w.x, acc);
                acc = fmaf(v.y, w.y, acc);
                acc = fmaf(v.z, w.z, acc);
                acc = fmaf(v.w, w.w, acc);
            }
            #pragma unroll
            for (int off = 16; off; off >>= 1)
                acc += __shfl_xor_sync(0xffffffffu, acc, off);
            if (lane == 0) d_s[b * LC + j] = acc + bias;
        }
    }
}

// ---------------------------------------------------------------------------
// Kernel 3: tau solve — R7's 3-barrier hierarchical 8-ary search (measured
// 12.7us solve, faster than redundant-total variant) + fused scatter tail.
// ---------------------------------------------------------------------------
__device__ __forceinline__ float clip01(float v) {
    return fminf(fmaxf(v, 0.f), 1.f);
}

__global__ void __launch_bounds__(512) tau_kernel(const int* __restrict__ qe_arr,
                                                  float* __restrict__ out) {
    int b = blockIdx.x;
    const int NT = 512;
    __shared__ float redf[16 * 7];
    __shared__ float sh_tot[8];
    int tid = threadIdx.x, warp = tid >> 5, lane = tid & 31;
    int len = d_len[b];
    const float* sp = d_s + b * LC;

    // register-resident values; invalid -> -1e5 (contributes 0, never max)
    float v[8];
    #pragma unroll
    for (int k = 0; k < 8; k++) {
        int i = tid + k * NT;
        v[k] = (i < len) ? sp[i] : -100000.0f;
    }

    // max and z_sum(0), fused block reduce
    float mx = -100000.0f, sum0 = 0.f;
    #pragma unroll
    for (int k = 0; k < 8; k++) {
        mx = fmaxf(mx, v[k]);
        sum0 += clip01(v[k]);
    }
    {
        #pragma unroll
        for (int off = 16; off; off >>= 1) {
            mx   = fmaxf(mx, __shfl_xor_sync(0xffffffffu, mx, off));
            sum0 += __shfl_xor_sync(0xffffffffu, sum0, off);
        }
        if (lane == 0) { redf[warp * 2] = mx; redf[warp * 2 + 1] = sum0; }
        __syncthreads();
        if (tid == 0) {
            float a = redf[0], s = redf[1];
            #pragma unroll
            for (int w = 1; w < 16; w++) {
                a = fmaxf(a, redf[w * 2]);
                s += redf[w * 2 + 1];
            }
            sh_tot[0] = a; sh_tot[1] = s;
        }
        __syncthreads();
        mx = sh_tot[0]; sum0 = sh_tot[1];
    }

    float tau = 0.f;
    if (sum0 > BUDGETF) {
        float lo = 0.f, hi = mx;
        for (int it = 0; it < 8; it++) {
            float step = (hi - lo) * 0.125f;
            float part[7];
            #pragma unroll
            for (int c = 0; c < 7; c++) part[c] = 0.f;
            #pragma unroll
            for (int k = 0; k < 8; k++) {
                float x = v[k] - lo;
                #pragma unroll
                for (int c = 0; c < 7; c++)
                    part[c] += clip01(x - (c + 1) * step);
            }
            #pragma unroll
            for (int c = 0; c < 7; c++) {
                #pragma unroll
                for (int off = 16; off; off >>= 1)
                    part[c] += __shfl_xor_sync(0xffffffffu, part[c], off);
            }
            if (lane == 0) {
                #pragma unroll
                for (int c = 0; c < 7; c++) redf[warp * 7 + c] = part[c];
            }
            __syncthreads();
            if (tid < 7) {
                float t = redf[tid];
                #pragma unroll
                for (int w = 1; w < 16; w++) t += redf[w * 7 + tid];
                sh_tot[tid] = t;
            }
            __syncthreads();
            // S non-increasing in tau: lo past candidates with S>BUDGET,
            // hi = first with S<=BUDGET (uniform across block).
            float nlo = lo, nhi = hi;
            bool crossed = false;
            #pragma unroll
            for (int c = 0; c < 7; c++) {
                float tc = lo + (c + 1) * step;
                if (!crossed) {
                    if (sh_tot[c] > BUDGETF) nlo = tc;
                    else { nhi = tc; crossed = true; }
                }
            }
            lo = nlo; hi = nhi;
            __syncthreads();   // protect redf/sh_tot before next round
        }
        tau = 0.5f * (lo + hi);
    }

    // fused scatter tail: out[b,p] = 1 | clip01(s[idx]-tau) | 0
    int qe = qe_arr[b];
    int clen = len - 1;
    for (int p = tid; p < LC; p += NT) {
        float r;
        if (p < qe) {
            r = 1.f;
        } else {
            int idx = p - qe + 1;                 // >= 1
            r = (idx <= clen) ? clip01(sp[idx] - tau) : 0.f;
        }
        out[b * LC + p] = r;
    }
}

// ---------------------------------------------------------------------------
extern "C" void kernel_launch(void* const* d_in, const int* in_sizes, int n_in,
                              void* d_out, int out_size) {
    const float* question = (const float*)d_in[0];  // [B,1,H]
    const float* context  = (const float*)d_in[1];  // [B,LC,H]
    const float* Wq       = (const float*)d_in[2];  // [H,P]
    const float* bq       = (const float*)d_in[3];  // [P]
    const float* Wc       = (const float*)d_in[4];  // [H,P]
    const float* bc       = (const float*)d_in[5];  // [P]
    const int*   maskp    = (const int*)d_in[6];    // [B,LC]
    const int*   qep      = (const int*)d_in[7];    // [B]
    float* out = (float*)d_out;                     // [B,MAXLEN]

    qproj_kernel<<<NB, 512>>>(question, Wq, bq, bc, maskp);
    dim3 gu(NB, 4);
    uproj_kernel<<<gu, 256>>>(Wc);
    score_kernel<<<SCORE_BLOCKS, 256>>>(context);
    tau_kernel<<<NB, 512>>>(qep, out);
}